// round 6
// baseline (speedup 1.0000x reference)
#include <cuda_runtime.h>
#include <cstdint>

// Grid is 128^3 logical; density padded to 130^3 plus zero guard bands so
// inactive rows can run the normal conv path against guaranteed-zero memory.
#define GRID_N   (128*128*128)            // 2,097,152
#define PADW     130
#define PGRID_N  (PADW*PADW*PADW)         // 2,197,000
#define GUARD    17104                    // > max |c_off| = 17031, 8B-aligned*4
#define DENS_ELEMS (GUARD + PGRID_N + GUARD)
#define BASE_SAFE  17050                  // all 27 taps land in guard / zero border
#define SCAN_BLOCKS 1024                  // 1024 * 256 * 8 = 2,097,152

// One fused zero-init region: [density floats w/ guards][active bytes]
__device__ __align__(16) unsigned char g_raw[DENS_ELEMS * 4 + GRID_N];
#define G_DENS   ((float*)g_raw)                         // index with GUARD offset
#define G_ACTIVE ((unsigned char*)(g_raw + DENS_ELEMS * 4))

__device__ unsigned int g_blocksums[SCAN_BLOCKS];
__device__ unsigned int g_blockoffs[SCAN_BLOCKS];
__device__ unsigned int g_count;
__device__ unsigned int g_cells[GRID_N];

// neighbor offsets in padded grid: di*16900 + dj*130 + dk, t=(di+1)*9+(dj+1)*3+(dk+1)
// (trailing zeros so the depth-2 prefetch can read t+2 unconditionally)
__constant__ int c_off[30] = {
    -17031,-17030,-17029,-16901,-16900,-16899,-16771,-16770,-16769,
      -131,  -130,  -129,    -1,     0,     1,   129,   130,   131,
     16769, 16770, 16771, 16899, 16900, 16901, 17029, 17030, 17031,
     0, 0, 0};

// ---------------------------------------------------------------------------
__global__ void scatter_kernel(const int* __restrict__ idx,
                               const float* __restrict__ feat, int n) {
    int i = blockIdx.x * blockDim.x + threadIdx.x;
    if (i >= n) return;
    int x = idx[3*i], y = idx[3*i+1], z = idx[3*i+2];
    int plin = ((x + 1) * PADW + (y + 1)) * PADW + (z + 1);
    atomicAdd(&G_DENS[GUARD + plin], feat[i]);
    #pragma unroll
    for (int di = -1; di <= 1; di++)
        #pragma unroll
        for (int dj = -1; dj <= 1; dj++)
            #pragma unroll
            for (int dk = -1; dk <= 1; dk++) {
                int nx = x + di, ny = y + dj, nz = z + dk;
                if ((unsigned)nx < 128u && (unsigned)ny < 128u && (unsigned)nz < 128u)
                    G_ACTIVE[(nx << 14) | (ny << 7) | nz] = 1;  // racy stores of 1: fine
            }
}

// ---- prefix scan over 2M flags: 3 kernels -------------------------------
__global__ void scan1_kernel() {
    int base = blockIdx.x * 2048 + threadIdx.x * 8;
    unsigned long long v = *(const unsigned long long*)(G_ACTIVE + base);
    unsigned s = (unsigned)((v * 0x0101010101010101ULL) >> 56);
    #pragma unroll
    for (int o = 16; o; o >>= 1) s += __shfl_down_sync(0xFFFFFFFFu, s, o);
    __shared__ unsigned ws[8];
    if ((threadIdx.x & 31) == 0) ws[threadIdx.x >> 5] = s;
    __syncthreads();
    if (threadIdx.x == 0) {
        unsigned t = 0;
        #pragma unroll
        for (int i = 0; i < 8; i++) t += ws[i];
        g_blocksums[blockIdx.x] = t;
    }
}

__global__ void scan2_kernel() {
    __shared__ unsigned sh[SCAN_BLOCKS];
    unsigned v = g_blocksums[threadIdx.x];
    sh[threadIdx.x] = v;
    __syncthreads();
    for (int o = 1; o < SCAN_BLOCKS; o <<= 1) {
        unsigned t = (threadIdx.x >= (unsigned)o) ? sh[threadIdx.x - o] : 0u;
        __syncthreads();
        sh[threadIdx.x] += t;
        __syncthreads();
    }
    g_blockoffs[threadIdx.x] = sh[threadIdx.x] - v;  // exclusive
    if (threadIdx.x == SCAN_BLOCKS - 1) g_count = sh[SCAN_BLOCKS - 1];
}

__global__ void scan3_kernel() {
    int base = blockIdx.x * 2048 + threadIdx.x * 8;
    unsigned long long v = *(const unsigned long long*)(G_ACTIVE + base);
    unsigned s = (unsigned)((v * 0x0101010101010101ULL) >> 56);
    unsigned lane = threadIdx.x & 31, wid = threadIdx.x >> 5;
    unsigned incl = s;
    #pragma unroll
    for (int o = 1; o < 32; o <<= 1) {
        unsigned t = __shfl_up_sync(0xFFFFFFFFu, incl, o);
        if (lane >= (unsigned)o) incl += t;
    }
    unsigned excl = incl - s;
    __shared__ unsigned ws[8];
    if (lane == 31) ws[wid] = incl;
    __syncthreads();
    unsigned woff = 0;
    for (unsigned i = 0; i < wid; i++) woff += ws[i];
    unsigned pos = g_blockoffs[blockIdx.x] + woff + excl;
    #pragma unroll
    for (int i = 0; i < 8; i++) {
        if ((v >> (i * 8)) & 1ULL) g_cells[pos++] = (unsigned)(base + i);
    }
}

// ---- fused output writer ------------------------------------------------
// Packed dual-fp32 FMA (sm_100+).
__device__ __forceinline__ void fma_x2(unsigned long long& d,
                                       unsigned long long a,
                                       unsigned long long b) {
    asm("fma.rn.f32x2 %0, %1, %2, %0;" : "+l"(d) : "l"(a), "l"(b));
}
__device__ __forceinline__ unsigned long long pack2(float f) {
    unsigned u = __float_as_uint(f);
    return ((unsigned long long)u << 32) | u;
}

// Thread = (cell-pair, channel-half): 2 cells x 32 channels each.
// Each LDS.128 weight load feeds both cells (halves LDS vs 1-cell/thread).
__global__ void __launch_bounds__(256)
feat_kernel(const float* __restrict__ kw,
            float* __restrict__ outc,   // [rows,3] coords (may be null)
            float* __restrict__ outf,   // [rows,64] features (may be null)
            int rows) {
    __shared__ float Ks[27 * 64];
    for (int i = threadIdx.x; i < 27 * 64; i += blockDim.x) Ks[i] = kw[i];
    __syncthreads();

    int gid = blockIdx.x * blockDim.x + threadIdx.x;
    int pr = gid >> 1;          // cell-pair index
    int p  = gid & 1;           // channel half
    int c0 = pr << 1;
    if (c0 >= rows) return;     // rows is even (n*27, n even)
    int c1 = c0 + 1;
    unsigned M = g_count;
    const float* __restrict__ D = (const float*)g_raw;

    bool a0 = c0 < (int)M, a1 = c1 < (int)M;
    unsigned lin0 = a0 ? g_cells[c0] : 0u;
    unsigned lin1 = a1 ? g_cells[c1] : 0u;
    int x0 = lin0 >> 14, y0 = (lin0 >> 7) & 127, z0 = lin0 & 127;
    int x1 = lin1 >> 14, y1 = (lin1 >> 7) & 127, z1 = lin1 & 127;

    if (outc && p == 0) {
        outc[3*c0 + 0] = a0 ? (float)x0 : 128.0f;
        outc[3*c0 + 1] = a0 ? (float)y0 : 128.0f;
        outc[3*c0 + 2] = a0 ? (float)z0 : 128.0f;
        outc[3*c1 + 0] = a1 ? (float)x1 : 128.0f;
        outc[3*c1 + 1] = a1 ? (float)y1 : 128.0f;
        outc[3*c1 + 2] = a1 ? (float)z1 : 128.0f;
    }
    if (!outf) return;

    // Inactive cells read guaranteed-zero guard/border memory -> zero output.
    int b0 = a0 ? (GUARD + ((x0 + 1) * PADW + (y0 + 1)) * PADW + (z0 + 1)) : BASE_SAFE;
    int b1 = a1 ? (GUARD + ((x1 + 1) * PADW + (y1 + 1)) * PADW + (z1 + 1)) : BASE_SAFE;

    unsigned long long acc[32];  // [0..16) cell0, [16..32) cell1 (32 ch each)
    #pragma unroll
    for (int j = 0; j < 32; j++) acc[j] = 0ULL;

    const float* Kp = Ks + p * 32;

    // Depth-2 rotating prefetch per cell (lane pairs load identical addrs).
    float d00 = D[b0 + c_off[0]], d01 = D[b0 + c_off[1]];
    float d10 = D[b1 + c_off[0]], d11 = D[b1 + c_off[1]];
    #pragma unroll 1
    for (int t = 0; t < 27; t++) {
        float n0 = D[b0 + c_off[t + 2]];   // trailing zero offsets: harmless
        float n1 = D[b1 + c_off[t + 2]];
        unsigned long long dd0 = pack2(d00);
        unsigned long long dd1 = pack2(d10);
        const ulonglong2* K2 = (const ulonglong2*)(Kp + t * 64);
        #pragma unroll
        for (int i = 0; i < 8; i++) {
            ulonglong2 kv = K2[i];          // 4 weights, broadcast LDS.128
            fma_x2(acc[2*i + 0],      kv.x, dd0);
            fma_x2(acc[2*i + 1],      kv.y, dd0);
            fma_x2(acc[16 + 2*i + 0], kv.x, dd1);
            fma_x2(acc[16 + 2*i + 1], kv.y, dd1);
        }
        d00 = d01; d01 = n0;
        d10 = d11; d11 = n1;
    }

    ulonglong2* o0 = (ulonglong2*)(outf + (size_t)c0 * 64 + p * 32);
    ulonglong2* o1 = (ulonglong2*)(outf + (size_t)c1 * 64 + p * 32);
    #pragma unroll
    for (int i = 0; i < 8; i++) {
        ulonglong2 v0; v0.x = acc[2*i];      v0.y = acc[2*i + 1];      o0[i] = v0;
        ulonglong2 v1; v1.x = acc[16 + 2*i]; v1.y = acc[16 + 2*i + 1]; o1[i] = v1;
    }
}

// ---------------------------------------------------------------------------
extern "C" void kernel_launch(void* const* d_in, const int* in_sizes, int n_in,
                              void* d_out, int out_size) {
    const int*   indices  = (const int*)d_in[0];    // [N,3] int32
    const float* features = (const float*)d_in[1];  // [N,1] float32
    const float* kw       = (const float*)d_in[2];  // [3,3,3,1,64] float32

    int n = in_sizes[0] / 3;
    int rows = n * 27;
    float* out = (float*)d_out;

    // Single fused zero-init (density + guards + active) -> 1 memset launch,
    // making feat_kernel the 6th launch (= the one ncu -s 5 -c 1 captures).
    void* p_raw = nullptr;
    cudaGetSymbolAddress(&p_raw, g_raw);
    cudaMemsetAsync(p_raw, 0, DENS_ELEMS * 4 + GRID_N);

    scatter_kernel<<<(n + 255) / 256, 256>>>(indices, features, n);
    scan1_kernel<<<SCAN_BLOCKS, 256>>>();
    scan2_kernel<<<1, SCAN_BLOCKS>>>();
    scan3_kernel<<<SCAN_BLOCKS, 256>>>();

    int rblocks = (rows + 255) / 256;   // one thread per row (2 threads/cell-pair)
    if (out_size == rows * 64) {
        feat_kernel<<<rblocks, 256>>>(kw, nullptr, out, rows);
    } else if (out_size == rows * 3) {
        feat_kernel<<<rblocks, 256>>>(kw, out, nullptr, rows);
    } else {
        // concatenated [uniq.ravel() | out_feat.ravel()] as float32
        feat_kernel<<<rblocks, 256>>>(kw, out, out + (size_t)rows * 3, rows);
    }
}

// round 7
// speedup vs baseline: 1.1214x; 1.1214x over previous
#include <cuda_runtime.h>
#include <cstdint>

// Grid is 128^3 logical; density is padded to 130^3 (1-voxel zero border).
#define GRID_N (128*128*128)          // 2,097,152
#define PADW   130
#define PGRID_N (PADW*PADW*PADW)      // 2,197,000
#define SCAN_BLOCKS 1024              // 1024 * 256 * 8 = 2,097,152

__device__ float g_pdensity[PGRID_N];
__device__ __align__(8) unsigned char g_active[GRID_N];
__device__ unsigned int g_blocksums[SCAN_BLOCKS];
__device__ unsigned int g_blockoffs[SCAN_BLOCKS];
__device__ unsigned int g_count;
__device__ unsigned int g_cells[GRID_N];

// neighbor offsets in padded grid: di*16900 + dj*130 + dk, t=(di+1)*9+(dj+1)*3+(dk+1)
// (three trailing zeros so depth-3 prefetch can read t+3 unconditionally)
__constant__ int c_off[30] = {
    -17031,-17030,-17029,-16901,-16900,-16899,-16771,-16770,-16769,
      -131,  -130,  -129,    -1,     0,     1,   129,   130,   131,
     16769, 16770, 16771, 16899, 16900, 16901, 17029, 17030, 17031,
     0, 0, 0};

// ---------------------------------------------------------------------------
// Scatter features into padded density grid + mark active (3x3x3) flags.
__global__ void scatter_kernel(const int* __restrict__ idx,
                               const float* __restrict__ feat, int n) {
    int i = blockIdx.x * blockDim.x + threadIdx.x;
    if (i >= n) return;
    int x = idx[3*i], y = idx[3*i+1], z = idx[3*i+2];
    int plin = ((x + 1) * PADW + (y + 1)) * PADW + (z + 1);
    atomicAdd(&g_pdensity[plin], feat[i]);
    #pragma unroll
    for (int di = -1; di <= 1; di++)
        #pragma unroll
        for (int dj = -1; dj <= 1; dj++)
            #pragma unroll
            for (int dk = -1; dk <= 1; dk++) {
                int nx = x + di, ny = y + dj, nz = z + dk;
                if ((unsigned)nx < 128u && (unsigned)ny < 128u && (unsigned)nz < 128u)
                    g_active[(nx << 14) | (ny << 7) | nz] = 1;  // racy stores of 1: fine
            }
}

// ---- prefix scan over 2M flags: 3 kernels -------------------------------
__global__ void scan1_kernel() {
    int base = blockIdx.x * 2048 + threadIdx.x * 8;
    unsigned long long v = *(const unsigned long long*)(g_active + base);
    unsigned s = (unsigned)((v * 0x0101010101010101ULL) >> 56);
    #pragma unroll
    for (int o = 16; o; o >>= 1) s += __shfl_down_sync(0xFFFFFFFFu, s, o);
    __shared__ unsigned ws[8];
    if ((threadIdx.x & 31) == 0) ws[threadIdx.x >> 5] = s;
    __syncthreads();
    if (threadIdx.x == 0) {
        unsigned t = 0;
        #pragma unroll
        for (int i = 0; i < 8; i++) t += ws[i];
        g_blocksums[blockIdx.x] = t;
    }
}

// warp-shuffle hierarchical scan of 1024 block sums
__global__ void scan2_kernel() {
    unsigned lane = threadIdx.x & 31, wid = threadIdx.x >> 5;
    unsigned v = g_blocksums[threadIdx.x];
    unsigned incl = v;
    #pragma unroll
    for (int o = 1; o < 32; o <<= 1) {
        unsigned t = __shfl_up_sync(0xFFFFFFFFu, incl, o);
        if (lane >= (unsigned)o) incl += t;
    }
    __shared__ unsigned ws[32];
    if (lane == 31) ws[wid] = incl;
    __syncthreads();
    if (wid == 0) {
        unsigned wv = ws[lane];
        unsigned winc = wv;
        #pragma unroll
        for (int o = 1; o < 32; o <<= 1) {
            unsigned t = __shfl_up_sync(0xFFFFFFFFu, winc, o);
            if (lane >= (unsigned)o) winc += t;
        }
        ws[lane] = winc - wv;  // exclusive warp offsets
        if (lane == 31) g_count = winc;
    }
    __syncthreads();
    g_blockoffs[threadIdx.x] = ws[wid] + incl - v;  // exclusive
}

__global__ void scan3_kernel() {
    int base = blockIdx.x * 2048 + threadIdx.x * 8;
    unsigned long long v = *(const unsigned long long*)(g_active + base);
    unsigned s = (unsigned)((v * 0x0101010101010101ULL) >> 56);
    unsigned lane = threadIdx.x & 31, wid = threadIdx.x >> 5;
    unsigned incl = s;
    #pragma unroll
    for (int o = 1; o < 32; o <<= 1) {
        unsigned t = __shfl_up_sync(0xFFFFFFFFu, incl, o);
        if (lane >= (unsigned)o) incl += t;
    }
    unsigned excl = incl - s;
    __shared__ unsigned ws[8];
    if (lane == 31) ws[wid] = incl;
    __syncthreads();
    unsigned woff = 0;
    for (unsigned i = 0; i < wid; i++) woff += ws[i];
    unsigned pos = g_blockoffs[blockIdx.x] + woff + excl;
    #pragma unroll
    for (int i = 0; i < 8; i++) {
        if ((v >> (i * 8)) & 1ULL) g_cells[pos++] = (unsigned)(base + i);
    }
}

// ---- fused output writer: coords + conv features ------------------------
// Packed dual-fp32 FMA (sm_100+): d = a*b+d on 2 lanes per instruction.
__device__ __forceinline__ void fma_x2(unsigned long long& d,
                                       unsigned long long a,
                                       unsigned long long b) {
    asm("fma.rn.f32x2 %0, %1, %2, %0;" : "+l"(d) : "l"(a), "l"(b));
}

// One thread per output row: 64 channels, depth-3 pipelined tap loop.
// minBlocksPerMultiprocessor=3 caps regs at ~85 -> 6 warps/SMSP so the
// FMA pipe (rt=3 for the 3-distinct-operand f32x2 form) stays saturated.
__global__ void __launch_bounds__(256, 3)
feat_kernel(const float* __restrict__ kw,
            float* __restrict__ outc,   // [rows,3] coords (may be null)
            float* __restrict__ outf,   // [rows,64] features (may be null)
            int rows) {
    __shared__ float Ks[27 * 64];
    for (int i = threadIdx.x; i < 27 * 64; i += blockDim.x) Ks[i] = kw[i];
    __syncthreads();

    int r = blockIdx.x * blockDim.x + threadIdx.x;
    if (r >= rows) return;
    unsigned M = g_count;

    if (r >= (int)M) {
        if (outc) {
            outc[3*r + 0] = 128.0f;
            outc[3*r + 1] = 128.0f;
            outc[3*r + 2] = 128.0f;
        }
        if (outf) {
            float4* o = (float4*)(outf + (size_t)r * 64);
            float4 z4 = make_float4(0.f, 0.f, 0.f, 0.f);
            #pragma unroll
            for (int i = 0; i < 16; i++) o[i] = z4;
        }
        return;
    }

    unsigned lin = g_cells[r];
    int x = lin >> 14, y = (lin >> 7) & 127, z = lin & 127;
    if (outc) {
        outc[3*r + 0] = (float)x;
        outc[3*r + 1] = (float)y;
        outc[3*r + 2] = (float)z;
    }
    if (!outf) return;

    int base = ((x + 1) * PADW + (y + 1)) * PADW + (z + 1);

    unsigned long long acc[32];  // 64 channels as 32 packed fp32 pairs
    #pragma unroll
    for (int j = 0; j < 32; j++) acc[j] = 0ULL;

    // Depth-3 rotating prefetch: ~3 loads in flight (low MLP_p1, no L1tex
    // queue pileup), hides L2 latency behind the FMA/LDS issue stream.
    float d0 = g_pdensity[base + c_off[0]];
    float d1 = g_pdensity[base + c_off[1]];
    float d2 = g_pdensity[base + c_off[2]];
    #pragma unroll 1
    for (int t = 0; t < 27; t++) {
        float dn = g_pdensity[base + c_off[t + 3]];  // trailing zeros: harmless
        unsigned du = __float_as_uint(d0);
        unsigned long long dd = ((unsigned long long)du << 32) | du;  // (d,d)
        const ulonglong2* K2 = (const ulonglong2*)(Ks + t * 64);
        #pragma unroll
        for (int i = 0; i < 16; i++) {
            ulonglong2 kv = K2[i];               // broadcast LDS.128
            fma_x2(acc[2*i + 0], kv.x, dd);
            fma_x2(acc[2*i + 1], kv.y, dd);
        }
        d0 = d1; d1 = d2; d2 = dn;
    }

    ulonglong2* o = (ulonglong2*)(outf + (size_t)r * 64);
    #pragma unroll
    for (int i = 0; i < 16; i++) {
        ulonglong2 v; v.x = acc[2*i]; v.y = acc[2*i + 1];
        o[i] = v;
    }
}

// ---------------------------------------------------------------------------
extern "C" void kernel_launch(void* const* d_in, const int* in_sizes, int n_in,
                              void* d_out, int out_size) {
    const int*   indices  = (const int*)d_in[0];    // [N,3] int32
    const float* features = (const float*)d_in[1];  // [N,1] float32
    const float* kw       = (const float*)d_in[2];  // [3,3,3,1,64] float32

    int n = in_sizes[0] / 3;
    int rows = n * 27;
    float* out = (float*)d_out;

    // zero density + active via memset nodes
    void* p_density = nullptr;
    void* p_active  = nullptr;
    cudaGetSymbolAddress(&p_density, g_pdensity);
    cudaGetSymbolAddress(&p_active,  g_active);
    cudaMemsetAsync(p_density, 0, PGRID_N * sizeof(float));
    cudaMemsetAsync(p_active,  0, GRID_N);

    scatter_kernel<<<(n + 255) / 256, 256>>>(indices, features, n);
    scan1_kernel<<<SCAN_BLOCKS, 256>>>();
    scan2_kernel<<<1, SCAN_BLOCKS>>>();
    scan3_kernel<<<SCAN_BLOCKS, 256>>>();

    int rblocks = (rows + 255) / 256;
    if (out_size == rows * 64) {
        feat_kernel<<<rblocks, 256>>>(kw, nullptr, out, rows);
    } else if (out_size == rows * 3) {
        feat_kernel<<<rblocks, 256>>>(kw, out, nullptr, rows);
    } else {
        // concatenated [uniq.ravel() | out_feat.ravel()] as float32
        feat_kernel<<<rblocks, 256>>>(kw, out, out + (size_t)rows * 3, rows);
    }
}